// round 9
// baseline (speedup 1.0000x reference)
#include <cuda_runtime.h>
#include <cuda_bf16.h>
#include <math.h>

// ---------------------------------------------------------------------------
// LSTM autoencoder, fp32, persistent per-layer kernels.
// Layers (I,H): (256,512)(512,256)(256,64)(64,256)(256,512)(512,256)
// B=64, T=256. One kernel per layer loops over t with a device-wide
// release/acquire barrier between steps. Weight slices live in smem for the
// whole layer. 13 graph nodes total.
// ---------------------------------------------------------------------------

#define BATCH 64
#define TSTEPS 256

// Sequence scratch, time-major [T][B][H]
__device__ float g_seq0[TSTEPS * BATCH * 512];
__device__ float g_seq1[TSTEPS * BATCH * 256];
__device__ float g_seq2[TSTEPS * BATCH * 64];
__device__ float g_seq3[TSTEPS * BATCH * 256];
__device__ float g_seq4[TSTEPS * BATCH * 512];
__device__ float g_seq5[TSTEPS * BATCH * 256];
// Cell state per layer [B][H] (max H = 512)
__device__ float g_cell[6 * BATCH * 512];
// Packed weights: per layer, [p = H/2][k = I+H][c = 8],
// column(c) = (c&3)*H + 2p + (c>>2)   (gate g = c&3, pair-member j = c>>2)
__device__ __align__(256) float g_packed[5128192];
// Grid-barrier counters, one per layer
__device__ unsigned g_barrier[8];

#define OFF0 0
#define OFF1 1572864
#define OFF2 2359296
#define OFF3 2441216
#define OFF4 2768896
#define OFF5 4341760

// ---------------------------------------------------------------------------
__global__ void init_counters(unsigned* c) {
    if (threadIdx.x < 8) c[threadIdx.x] = 0;
}

// Repack W [I,4H] and U [H,4H] into per-CTA contiguous slices.
template <int I, int H>
__global__ void repack_kernel(const float* __restrict__ W,
                              const float* __restrict__ U,
                              float* __restrict__ out) {
    constexpr int K = I + H;
    constexpr int N4 = 4 * H;
    const int total = (H / 2) * K * 8;
    for (int idx = blockIdx.x * blockDim.x + threadIdx.x; idx < total;
         idx += gridDim.x * blockDim.x) {
        int c = idx & 7;
        int k = (idx >> 3) % K;
        int p = idx / (8 * K);
        int col = (c & 3) * H + 2 * p + (c >> 2);
        out[idx] = (k < I) ? W[k * N4 + col] : U[(k - I) * N4 + col];
    }
}

// Device-wide barrier: monotonic counter, release arrive / acquire spin.
__device__ __forceinline__ void grid_bar(unsigned* cnt, unsigned target) {
    __syncthreads();
    if (threadIdx.x == 0) {
        asm volatile("red.release.gpu.global.add.u32 [%0], 1;"
                     :: "l"(cnt) : "memory");
        unsigned v;
        do {
            asm volatile("ld.acquire.gpu.global.u32 %0, [%1];"
                         : "=r"(v) : "l"(cnt) : "memory");
        } while (v < target);
    }
    __syncthreads();
}

// ---------------------------------------------------------------------------
// Persistent layer kernel. Grid: H/2 CTAs (one h-column pair each), 128 thr.
// Thread: row r = tid&63, K-half kh = tid>>6; 8 z-cols per thread; the two
// K-halves reduce through smem; kh==0 quarter applies gates.
// XSTRIDED: layer-0 input x is [B][T][I] (row stride 65536, step offset 256);
// otherwise input is a time-major seq buffer [T][B][I].
// ---------------------------------------------------------------------------
template <int I, int H, bool TANH, bool XSTRIDED>
__global__ __launch_bounds__(128) void lstm_layer_kernel(
    const float* __restrict__ xin,
    float* __restrict__ hseq,
    float* __restrict__ cbuf,
    const float* __restrict__ Bp,
    const float* __restrict__ bias,
    unsigned* __restrict__ cnt,
    float* __restrict__ finalOut) {
    constexpr int K = I + H;
    __shared__ __align__(16) float sB[K * 8];
    __shared__ float sA[32][65];
    __shared__ float sRed[BATCH * 8];

    const int tid = threadIdx.x;
    const int p = blockIdx.x;
    const int r = tid & 63;
    const int kh = tid >> 6;
    const unsigned nCTA = gridDim.x;

    // Load this CTA's packed weight slice once for the whole layer.
    {
        const float4* src = reinterpret_cast<const float4*>(Bp + (size_t)p * K * 8);
        float4* dst = reinterpret_cast<float4*>(sB);
        for (int i = tid; i < 2 * K; i += 128) dst[i] = src[i];
    }
    // Preload bias for this CTA's two columns (broadcast through regs).
    const int n0 = 2 * p;
    float bi0 = bias[0 * H + n0], bf0 = bias[1 * H + n0];
    float bg0 = bias[2 * H + n0], bo0 = bias[3 * H + n0];
    float bi1 = bias[0 * H + n0 + 1], bf1 = bias[1 * H + n0 + 1];
    float bg1 = bias[2 * H + n0 + 1], bo1 = bias[3 * H + n0 + 1];
    __syncthreads();

    for (int t = 0; t < TSTEPS; ++t) {
        const float* xP = XSTRIDED ? (xin + (size_t)t * 256)
                                   : (xin + (size_t)t * BATCH * I);
        const int xs = XSTRIDED ? 65536 : I;
        const float* hP = hseq + (size_t)(t - 1) * BATCH * H;  // valid for t>0
        const int Keff = (t == 0) ? I : K;

        float acc[8] = {0.f, 0.f, 0.f, 0.f, 0.f, 0.f, 0.f, 0.f};

        for (int kc = 0; kc < Keff; kc += 32) {
            const float* srcA;
            int stride;
            if (kc < I) { srcA = xP + kc;       stride = xs; }
            else        { srcA = hP + (kc - I); stride = H; }
#pragma unroll
            for (int i = 0; i < 16; ++i) {
                int idx = i * 128 + tid;
                int kk = idx & 31;
                int row = idx >> 5;
                sA[kk][row] = srcA[(size_t)row * stride + kk];
            }
            __syncthreads();

#pragma unroll
            for (int kk2 = 0; kk2 < 16; ++kk2) {
                const int kk = (kh << 4) + kk2;
                const float a = sA[kk][r];
                const float4 b0 =
                    *reinterpret_cast<const float4*>(&sB[(kc + kk) * 8]);
                const float4 b1 =
                    *reinterpret_cast<const float4*>(&sB[(kc + kk) * 8 + 4]);
                acc[0] = fmaf(a, b0.x, acc[0]);
                acc[1] = fmaf(a, b0.y, acc[1]);
                acc[2] = fmaf(a, b0.z, acc[2]);
                acc[3] = fmaf(a, b0.w, acc[3]);
                acc[4] = fmaf(a, b1.x, acc[4]);
                acc[5] = fmaf(a, b1.y, acc[5]);
                acc[6] = fmaf(a, b1.z, acc[6]);
                acc[7] = fmaf(a, b1.w, acc[7]);
            }
            __syncthreads();
        }

        if (kh == 1) {
#pragma unroll
            for (int c = 0; c < 8; ++c) sRed[r * 8 + c] = acc[c];
        }
        __syncthreads();

        if (kh == 0) {
#pragma unroll
            for (int c = 0; c < 8; ++c) acc[c] += sRed[r * 8 + c];

            // column n0 (j=0)
            {
                float zi = acc[0] + bi0, zf = acc[1] + bf0;
                float zg = acc[2] + bg0, zo = acc[3] + bo0;
                float ig = 1.f / (1.f + expf(-zi));
                float fg = 1.f / (1.f + expf(-zf));
                float gg = TANH ? tanhf(zg) : fmaxf(zg, 0.f);
                float og = 1.f / (1.f + expf(-zo));
                float cp = (t == 0) ? 0.f : cbuf[r * H + n0];
                float cn = fg * cp + ig * gg;
                cbuf[r * H + n0] = cn;
                float hn = og * (TANH ? tanhf(cn) : fmaxf(cn, 0.f));
                hseq[((size_t)t * BATCH + r) * H + n0] = hn;
                if (finalOut && t == TSTEPS - 1) finalOut[r * H + n0] = hn;
            }
            // column n0+1 (j=1)
            {
                float zi = acc[4] + bi1, zf = acc[5] + bf1;
                float zg = acc[6] + bg1, zo = acc[7] + bo1;
                float ig = 1.f / (1.f + expf(-zi));
                float fg = 1.f / (1.f + expf(-zf));
                float gg = TANH ? tanhf(zg) : fmaxf(zg, 0.f);
                float og = 1.f / (1.f + expf(-zo));
                float cp = (t == 0) ? 0.f : cbuf[r * H + n0 + 1];
                float cn = fg * cp + ig * gg;
                cbuf[r * H + n0 + 1] = cn;
                float hn = og * (TANH ? tanhf(cn) : fmaxf(cn, 0.f));
                hseq[((size_t)t * BATCH + r) * H + n0 + 1] = hn;
                if (finalOut && t == TSTEPS - 1) finalOut[r * H + n0 + 1] = hn;
            }
        }

        grid_bar(cnt, (unsigned)(t + 1) * nCTA);
    }
}

// ---------------------------------------------------------------------------
extern "C" void kernel_launch(void* const* d_in, const int* in_sizes, int n_in,
                              void* d_out, int out_size) {
    (void)in_sizes; (void)n_in; (void)out_size;

    const float* x = (const float*)d_in[0];
    const float* W[6];
    const float* U[6];
    const float* b[6];
    for (int l = 0; l < 6; ++l) {
        W[l] = (const float*)d_in[1 + 3 * l];
        U[l] = (const float*)d_in[2 + 3 * l];
        b[l] = (const float*)d_in[3 + 3 * l];
    }

    float *seq0, *seq1, *seq2, *seq3, *seq4, *seq5, *cell, *pk;
    unsigned* bar;
    cudaGetSymbolAddress((void**)&seq0, g_seq0);
    cudaGetSymbolAddress((void**)&seq1, g_seq1);
    cudaGetSymbolAddress((void**)&seq2, g_seq2);
    cudaGetSymbolAddress((void**)&seq3, g_seq3);
    cudaGetSymbolAddress((void**)&seq4, g_seq4);
    cudaGetSymbolAddress((void**)&seq5, g_seq5);
    cudaGetSymbolAddress((void**)&cell, g_cell);
    cudaGetSymbolAddress((void**)&pk, g_packed);
    cudaGetSymbolAddress((void**)&bar, g_barrier);

    init_counters<<<1, 32>>>(bar);

    repack_kernel<256, 512><<<256, 256>>>(W[0], U[0], pk + OFF0);
    repack_kernel<512, 256><<<256, 256>>>(W[1], U[1], pk + OFF1);
    repack_kernel<256, 64><<<64, 256>>>(W[2], U[2], pk + OFF2);
    repack_kernel<64, 256><<<128, 256>>>(W[3], U[3], pk + OFF3);
    repack_kernel<256, 512><<<256, 256>>>(W[4], U[4], pk + OFF4);
    repack_kernel<512, 256><<<256, 256>>>(W[5], U[5], pk + OFF5);

    lstm_layer_kernel<256, 512, false, true><<<256, 128>>>(
        x, seq0, cell + 0 * BATCH * 512, pk + OFF0, b[0], bar + 0, nullptr);
    lstm_layer_kernel<512, 256, false, false><<<128, 128>>>(
        seq0, seq1, cell + 1 * BATCH * 512, pk + OFF1, b[1], bar + 1, nullptr);
    lstm_layer_kernel<256, 64, false, false><<<32, 128>>>(
        seq1, seq2, cell + 2 * BATCH * 512, pk + OFF2, b[2], bar + 2, nullptr);
    lstm_layer_kernel<64, 256, false, false><<<128, 128>>>(
        seq2, seq3, cell + 3 * BATCH * 512, pk + OFF3, b[3], bar + 3, nullptr);
    lstm_layer_kernel<256, 512, false, false><<<256, 128>>>(
        seq3, seq4, cell + 4 * BATCH * 512, pk + OFF4, b[4], bar + 4, nullptr);
    lstm_layer_kernel<512, 256, true, false><<<128, 128>>>(
        seq4, seq5, cell + 5 * BATCH * 512, pk + OFF5, b[5], bar + 5,
        (float*)d_out);
}

// round 10
// speedup vs baseline: 3.6560x; 3.6560x over previous
#include <cuda_runtime.h>
#include <math.h>
#include <stdint.h>

// ---------------------------------------------------------------------------
// LSTM autoencoder, fp32, SINGLE fused persistent kernel (layer wavefront).
// Layers (I,H): L0(256,512) L1(512,256) L2(256,64) L3(64,256) L4(256,512)
//               L5(512,256).  B=64, T=256.
// Global step s: layer l computes t = s - l. One grid-wide barrier per step.
// Per CTA: 16 z-columns x 64 rows, K streamed in 64-chunks via cp.async,
// double buffered. Thread tile 4 rows x 2 cols (cols cg and cg+8).
// ---------------------------------------------------------------------------

#define BATCH 64
#define TSTEPS 256
#define NCTA 464
#define GSTEPS (TSTEPS + 5)

// Sequence scratch, time-major [T][B][H]
__device__ float g_seq0[TSTEPS * BATCH * 512];
__device__ float g_seq1[TSTEPS * BATCH * 256];
__device__ float g_seq2[TSTEPS * BATCH * 64];
__device__ float g_seq3[TSTEPS * BATCH * 256];
__device__ float g_seq4[TSTEPS * BATCH * 512];
__device__ float g_seq5[TSTEPS * BATCH * 256];
__device__ float g_cell[6 * BATCH * 512];
// Packed weights per layer: [g][K/4][16][4] floats, c = gate*4 + hc,
// element (k=4*k4+e, col = gate*H + g*4 + hc).
__device__ __align__(256) float g_packed[5128192];
__device__ unsigned g_barrier[4];

#define OFF0 0
#define OFF1 1572864
#define OFF2 2359296
#define OFF3 2441216
#define OFF4 2768896
#define OFF5 4341760

// ---------------------------------------------------------------------------
__global__ void init_counters() {
    if (threadIdx.x < 4) g_barrier[threadIdx.x] = 0;
}

template <int I, int H>
__global__ void repack_kernel(const float* __restrict__ W,
                              const float* __restrict__ U,
                              float* __restrict__ out) {
    constexpr int K = I + H;
    constexpr int N4 = 4 * H;
    const int total = K * N4;
    for (int idx = blockIdx.x * blockDim.x + threadIdx.x; idx < total;
         idx += gridDim.x * blockDim.x) {
        int e = idx & 3;
        int c = (idx >> 2) & 15;
        int k4 = (idx >> 6) % (K >> 2);
        int g = idx / (16 * K);
        int k = k4 * 4 + e;
        int gate = c >> 2;
        int hc = c & 3;
        int col = gate * H + g * 4 + hc;
        out[idx] = (k < I) ? W[k * N4 + col] : U[(k - I) * N4 + col];
    }
}

// ---------------------------------------------------------------------------
__device__ __forceinline__ void cp16(uint32_t saddr, const void* gaddr) {
    asm volatile("cp.async.cg.shared.global [%0], [%1], 16;"
                 :: "r"(saddr), "l"(gaddr) : "memory");
}
__device__ __forceinline__ void cp_commit() {
    asm volatile("cp.async.commit_group;" ::: "memory");
}
__device__ __forceinline__ void cp_wait1() {
    asm volatile("cp.async.wait_group 1;" ::: "memory");
}

__device__ __forceinline__ void grid_bar(unsigned* cnt, unsigned target) {
    __syncthreads();
    if (threadIdx.x == 0) {
        asm volatile("red.release.gpu.global.add.u32 [%0], 1;"
                     :: "l"(cnt) : "memory");
        unsigned v;
        do {
            asm volatile("ld.acquire.gpu.global.u32 %0, [%1];"
                         : "=r"(v) : "l"(cnt) : "memory");
        } while (v < target);
    }
    __syncthreads();
}

// ---------------------------------------------------------------------------
// One (layer, t) step for one CTA covering h-cols [g*4, g*4+4) (16 z-cols).
// sA: 2 * 64 rows * 17 float4 (row = 64 k floats + 4 pad).
// sB: 2 * 256 float4  ([k4=16][c=16]).
// sZ: 64 * 17 floats.
// ---------------------------------------------------------------------------
template <int I, int H, bool TANH, bool XSTRIDED, bool OUT>
__device__ __forceinline__ void layer_step(
    int g, int t,
    const float* __restrict__ xin, float* __restrict__ hseq,
    float* __restrict__ cbuf, const float* __restrict__ Bp,
    const float* __restrict__ bias, float* __restrict__ outp,
    float4* sA, float4* sB, float* sZ) {
    constexpr int K = I + H;
    static_assert((I & 63) == 0 && (K & 63) == 0, "chunking");
    const int tid = threadIdx.x;
    const int rg = tid >> 3;        // 0..15 (row group of 4)
    const int cg = tid & 7;         // 0..7  (cols cg, cg+8)

    const float* xP = XSTRIDED ? (xin + (size_t)t * 256)
                               : (xin + (size_t)t * BATCH * I);
    const int xs = XSTRIDED ? 65536 : I;
    const float* hP = hseq + (size_t)(t - 1) * BATCH * H;  // only if t>0
    const int nch = ((t == 0) ? I : K) >> 6;
    const float* BpG = Bp + (size_t)g * K * 16;

    auto issue = [&](int c) {
        if (c < nch) {
            const int kc = c << 6;
            const float* asrc;
            int stride;
            if (kc < I) { asrc = xP + kc;       stride = xs; }
            else        { asrc = hP + (kc - I); stride = H; }
            uint32_t sa = (uint32_t)__cvta_generic_to_shared(
                sA + (size_t)(c & 1) * (64 * 17));
#pragma unroll
            for (int i = 0; i < 8; ++i) {
                int q = tid + i * 128;
                int row = q >> 4, j = q & 15;
                cp16(sa + (uint32_t)(row * 17 + j) * 16,
                     asrc + (size_t)row * stride + j * 4);
            }
            uint32_t sb = (uint32_t)__cvta_generic_to_shared(
                sB + (size_t)(c & 1) * 256);
            const float* bsrc = BpG + (size_t)kc * 16;
#pragma unroll
            for (int i = 0; i < 2; ++i) {
                int q = tid + i * 128;
                cp16(sb + (uint32_t)q * 16, bsrc + (size_t)q * 4);
            }
        }
        cp_commit();
    };

    float acc[4][2][1];
    float a0c[4], a1c[4];  // not used; keep simple accs below
    (void)a0c; (void)a1c;
    float ac[8];
#pragma unroll
    for (int i = 0; i < 8; ++i) ac[i] = 0.f;

    issue(0);
    issue(1);
    (void)acc;

    for (int c = 0; c < nch; ++c) {
        cp_wait1();
        __syncthreads();
        const float4* A4 = sA + (size_t)(c & 1) * (64 * 17);
        const float4* B4 = sB + (size_t)(c & 1) * 256;
#pragma unroll
        for (int k4 = 0; k4 < 16; ++k4) {
            float4 b0 = B4[k4 * 16 + cg];
            float4 b1 = B4[k4 * 16 + cg + 8];
#pragma unroll
            for (int r = 0; r < 4; ++r) {
                float4 a = A4[(rg * 4 + r) * 17 + k4];
                float s0 = ac[r * 2 + 0];
                float s1 = ac[r * 2 + 1];
                s0 = fmaf(a.x, b0.x, s0);
                s1 = fmaf(a.x, b1.x, s1);
                s0 = fmaf(a.y, b0.y, s0);
                s1 = fmaf(a.y, b1.y, s1);
                s0 = fmaf(a.z, b0.z, s0);
                s1 = fmaf(a.z, b1.z, s1);
                s0 = fmaf(a.w, b0.w, s0);
                s1 = fmaf(a.w, b1.w, s1);
                ac[r * 2 + 0] = s0;
                ac[r * 2 + 1] = s1;
            }
        }
        __syncthreads();
        issue(c + 2);
    }

    // Stage z into smem: z[row][c], c = packed col index (gate*4+hc).
#pragma unroll
    for (int r = 0; r < 4; ++r) {
        int row = rg * 4 + r;
        sZ[row * 17 + cg] = ac[r * 2 + 0];
        sZ[row * 17 + cg + 8] = ac[r * 2 + 1];
    }
    __syncthreads();

    // Gate phase: thread -> (row = tid>>1, two hc's).
    {
        const int row = tid >> 1;
        const int hcb = (tid & 1) * 2;
#pragma unroll
        for (int u = 0; u < 2; ++u) {
            const int hc = hcb + u;
            const int hcol = g * 4 + hc;
            float zi = sZ[row * 17 + hc] + bias[hcol];
            float zf = sZ[row * 17 + 4 + hc] + bias[H + hcol];
            float zg = sZ[row * 17 + 8 + hc] + bias[2 * H + hcol];
            float zo = sZ[row * 17 + 12 + hc] + bias[3 * H + hcol];
            float ig = 1.f / (1.f + expf(-zi));
            float fg = 1.f / (1.f + expf(-zf));
            float gg = TANH ? tanhf(zg) : fmaxf(zg, 0.f);
            float og = 1.f / (1.f + expf(-zo));
            float cp_ = (t == 0) ? 0.f : cbuf[row * H + hcol];
            float cn = fg * cp_ + ig * gg;
            cbuf[row * H + hcol] = cn;
            float hn = og * (TANH ? tanhf(cn) : fmaxf(cn, 0.f));
            hseq[((size_t)t * BATCH + row) * H + hcol] = hn;
            if (OUT && t == TSTEPS - 1) outp[row * H + hcol] = hn;
        }
    }
    // grid_bar provides the closing __syncthreads.
}

// ---------------------------------------------------------------------------
// Fused persistent kernel. Block order interleaves heavy/light layers for
// SM balance: [L0:0-127][L3:128-191][L1:192-255][L2:256-271][L4:272-399]
// [L5:400-463].
// ---------------------------------------------------------------------------
__global__ __launch_bounds__(128, 4) void fused_kernel(
    const float* __restrict__ x,
    const float* __restrict__ b0, const float* __restrict__ b1,
    const float* __restrict__ b2, const float* __restrict__ b3,
    const float* __restrict__ b4, const float* __restrict__ b5,
    float* __restrict__ outp) {
    __shared__ float4 sA[2 * 64 * 17];
    __shared__ float4 sB[2 * 256];
    __shared__ float sZ[64 * 17];

    const int bid = blockIdx.x;
    unsigned* cnt = &g_barrier[0];

    for (int s = 0; s < GSTEPS; ++s) {
        if (bid < 128) {
            int t = s;
            if ((unsigned)t < TSTEPS)
                layer_step<256, 512, false, true, false>(
                    bid, t, x, g_seq0, g_cell + 0 * BATCH * 512,
                    g_packed + OFF0, b0, nullptr, sA, sB, sZ);
        } else if (bid < 192) {
            int t = s - 3;
            if ((unsigned)t < TSTEPS)
                layer_step<64, 256, false, false, false>(
                    bid - 128, t, g_seq2, g_seq3, g_cell + 3 * BATCH * 512,
                    g_packed + OFF3, b3, nullptr, sA, sB, sZ);
        } else if (bid < 256) {
            int t = s - 1;
            if ((unsigned)t < TSTEPS)
                layer_step<512, 256, false, false, false>(
                    bid - 192, t, g_seq0, g_seq1, g_cell + 1 * BATCH * 512,
                    g_packed + OFF1, b1, nullptr, sA, sB, sZ);
        } else if (bid < 272) {
            int t = s - 2;
            if ((unsigned)t < TSTEPS)
                layer_step<256, 64, false, false, false>(
                    bid - 256, t, g_seq1, g_seq2, g_cell + 2 * BATCH * 512,
                    g_packed + OFF2, b2, nullptr, sA, sB, sZ);
        } else if (bid < 400) {
            int t = s - 4;
            if ((unsigned)t < TSTEPS)
                layer_step<256, 512, false, false, false>(
                    bid - 272, t, g_seq3, g_seq4, g_cell + 4 * BATCH * 512,
                    g_packed + OFF4, b4, nullptr, sA, sB, sZ);
        } else {
            int t = s - 5;
            if ((unsigned)t < TSTEPS)
                layer_step<512, 256, true, false, true>(
                    bid - 400, t, g_seq4, g_seq5, g_cell + 5 * BATCH * 512,
                    g_packed + OFF5, b5, outp, sA, sB, sZ);
        }
        grid_bar(cnt, (unsigned)(s + 1) * NCTA);
    }
}

// ---------------------------------------------------------------------------
extern "C" void kernel_launch(void* const* d_in, const int* in_sizes, int n_in,
                              void* d_out, int out_size) {
    (void)in_sizes; (void)n_in; (void)out_size;

    const float* x = (const float*)d_in[0];
    const float* W[6];
    const float* U[6];
    const float* b[6];
    for (int l = 0; l < 6; ++l) {
        W[l] = (const float*)d_in[1 + 3 * l];
        U[l] = (const float*)d_in[2 + 3 * l];
        b[l] = (const float*)d_in[3 + 3 * l];
    }

    float* pk;
    cudaGetSymbolAddress((void**)&pk, g_packed);

    init_counters<<<1, 32>>>();

    repack_kernel<256, 512><<<256, 256>>>(W[0], U[0], pk + OFF0);
    repack_kernel<512, 256><<<256, 256>>>(W[1], U[1], pk + OFF1);
    repack_kernel<256, 64><<<64, 256>>>(W[2], U[2], pk + OFF2);
    repack_kernel<64, 256><<<128, 256>>>(W[3], U[3], pk + OFF3);
    repack_kernel<256, 512><<<256, 256>>>(W[4], U[4], pk + OFF4);
    repack_kernel<512, 256><<<256, 256>>>(W[5], U[5], pk + OFF5);

    fused_kernel<<<NCTA, 128>>>(x, b[0], b[1], b[2], b[3], b[4], b[5],
                                (float*)d_out);
}

// round 12
// speedup vs baseline: 3.6622x; 1.0017x over previous
#include <cuda_runtime.h>
#include <math.h>
#include <stdint.h>

// ---------------------------------------------------------------------------
// LSTM autoencoder, fp32, fused persistent wavefront kernel, FFMA2 inner loop.
// Layers (I,H): L0(256,512) L1(512,256) L2(256,64) L3(64,256) L4(256,512)
//               L5(512,256).  B=64, T=256.
// Global step s: layer l computes t = s-l; one grid barrier per step.
// 424 CTAs (heavy layers: 1 tile of 16 z-cols; L2/L3: 2 tiles per CTA).
// Thread tile: rows {r2, r2+32} x 4 cols as two f32x2 pairs (fma.rn.f32x2).
// __launch_bounds__(128, 3) guarantees >=3 CTAs/SM so all 424 are resident
// (grid barrier requires full co-residency; R11 hang was regs>170 -> 2/SM).
// ---------------------------------------------------------------------------

#define BATCH 64
#define TSTEPS 256
#define NCTA 424
#define GSTEPS (TSTEPS + 5)

typedef unsigned long long ull;

__device__ float g_seq0[TSTEPS * BATCH * 512];
__device__ float g_seq1[TSTEPS * BATCH * 256];
__device__ float g_seq2[TSTEPS * BATCH * 64];
__device__ float g_seq3[TSTEPS * BATCH * 256];
__device__ float g_seq4[TSTEPS * BATCH * 512];
__device__ float g_seq5[TSTEPS * BATCH * 256];
__device__ float g_cell[6 * BATCH * 512];
// Packed weights per layer: [g][k][tc] floats, tc = gate*4 + hc,
// col = gate*H + g*4 + hc.
__device__ __align__(256) float g_packed[5128192];
__device__ unsigned g_barrier[4];

#define OFF0 0
#define OFF1 1572864
#define OFF2 2359296
#define OFF3 2441216
#define OFF4 2768896
#define OFF5 4341760

// ---------------------------------------------------------------------------
__global__ void init_counters() {
    if (threadIdx.x < 4) g_barrier[threadIdx.x] = 0;
}

template <int I, int H>
__global__ void repack_kernel(const float* __restrict__ W,
                              const float* __restrict__ U,
                              float* __restrict__ out) {
    constexpr int K = I + H;
    constexpr int N4 = 4 * H;
    const int total = K * N4;
    for (int idx = blockIdx.x * blockDim.x + threadIdx.x; idx < total;
         idx += gridDim.x * blockDim.x) {
        int tc = idx & 15;
        int k = (idx >> 4) % K;
        int g = idx / (16 * K);
        int gate = tc >> 2;
        int hc = tc & 3;
        int col = gate * H + g * 4 + hc;
        out[idx] = (k < I) ? W[k * N4 + col] : U[(k - I) * N4 + col];
    }
}

// ---------------------------------------------------------------------------
__device__ __forceinline__ void cp16(uint32_t saddr, const void* gaddr) {
    asm volatile("cp.async.cg.shared.global [%0], [%1], 16;"
                 :: "r"(saddr), "l"(gaddr) : "memory");
}
__device__ __forceinline__ void cp_commit() {
    asm volatile("cp.async.commit_group;" ::: "memory");
}
__device__ __forceinline__ void cp_wait1() {
    asm volatile("cp.async.wait_group 1;" ::: "memory");
}

__device__ __forceinline__ ull pack2(float v) {
    ull r;
    asm("mov.b64 %0, {%1, %1};" : "=l"(r) : "f"(v));
    return r;
}
__device__ __forceinline__ float2 unp2(ull v) {
    float2 f;
    asm("mov.b64 {%0, %1}, %2;" : "=f"(f.x), "=f"(f.y) : "l"(v));
    return f;
}
__device__ __forceinline__ void ffma2(ull& d, ull a, ull b) {
    asm("fma.rn.f32x2 %0, %1, %2, %3;" : "=l"(d) : "l"(a), "l"(b), "l"(d));
}

__device__ __forceinline__ void grid_bar(unsigned* cnt, unsigned target) {
    __syncthreads();
    if (threadIdx.x == 0) {
        asm volatile("red.release.gpu.global.add.u32 [%0], 1;"
                     :: "l"(cnt) : "memory");
        unsigned v;
        do {
            asm volatile("ld.acquire.gpu.global.u32 %0, [%1];"
                         : "=r"(v) : "l"(cnt) : "memory");
        } while (v < target);
    }
    __syncthreads();
}

// ---------------------------------------------------------------------------
// One (layer, t) tile step: h-cols [g*4, g*4+4) i.e. 16 packed z-cols.
// sA: 2 buffers of 64 rows x 17 float4 (64 k floats + pad).
// sB: 2 buffers of 256 float4 ([k=64][cgrp=4]).
// sZ: 64 x 17 floats.
// ---------------------------------------------------------------------------
template <int I, int H, bool TANH, bool XSTRIDED, bool OUT>
__device__ __forceinline__ void layer_step(
    int g, int t,
    const float* __restrict__ xin, float* __restrict__ hseq,
    float* __restrict__ cbuf, const float* __restrict__ Bp,
    const float* __restrict__ bias, float* __restrict__ outp,
    float4* sA, float4* sB, float* sZ) {
    constexpr int K = I + H;
    static_assert((I & 63) == 0 && (K & 63) == 0, "chunking");
    const int tid = threadIdx.x;
    const int r2 = tid >> 2;     // rows r2 and r2+32
    const int cgrp = tid & 3;    // packed cols 4*cgrp .. 4*cgrp+3

    const float* xP = XSTRIDED ? (xin + (size_t)t * 256)
                               : (xin + (size_t)t * BATCH * I);
    const int xs = XSTRIDED ? 65536 : I;
    const float* hP = hseq + (size_t)(t - 1) * BATCH * H;  // only if t>0
    const int nch = ((t == 0) ? I : K) >> 6;
    const float* BpG = Bp + (size_t)g * K * 16;

    auto issue = [&](int c) {
        if (c < nch) {
            const int kc = c << 6;
            const float* asrc;
            int stride;
            if (kc < I) { asrc = xP + kc;       stride = xs; }
            else        { asrc = hP + (kc - I); stride = H; }
            uint32_t sa = (uint32_t)__cvta_generic_to_shared(
                sA + (size_t)(c & 1) * (64 * 17));
#pragma unroll
            for (int i = 0; i < 8; ++i) {
                int q = tid + i * 128;
                int row = q >> 4, j = q & 15;
                cp16(sa + (uint32_t)(row * 17 + j) * 16,
                     asrc + (size_t)row * stride + j * 4);
            }
            uint32_t sb = (uint32_t)__cvta_generic_to_shared(
                sB + (size_t)(c & 1) * 256);
            const float* bsrc = BpG + (size_t)kc * 16;
#pragma unroll
            for (int i = 0; i < 2; ++i) {
                int q = tid + i * 128;
                cp16(sb + (uint32_t)q * 16, bsrc + (size_t)q * 4);
            }
        }
        cp_commit();
    };

    ull a00 = 0ULL, a01 = 0ULL, a10 = 0ULL, a11 = 0ULL;

    issue(0);
    issue(1);

    for (int c = 0; c < nch; ++c) {
        cp_wait1();
        __syncthreads();
        const float4* A4 = sA + (size_t)(c & 1) * (64 * 17);
        const ulonglong2* B2 =
            reinterpret_cast<const ulonglong2*>(sB + (size_t)(c & 1) * 256);
#pragma unroll 4
        for (int k4 = 0; k4 < 16; ++k4) {
            float4 alo = A4[r2 * 17 + k4];
            float4 ahi = A4[(r2 + 32) * 17 + k4];
            const float* alof = reinterpret_cast<const float*>(&alo);
            const float* ahif = reinterpret_cast<const float*>(&ahi);
#pragma unroll
            for (int e = 0; e < 4; ++e) {
                ulonglong2 bb = B2[(k4 * 4 + e) * 4 + cgrp];
                ull pl = pack2(alof[e]);
                ull ph = pack2(ahif[e]);
                ffma2(a00, pl, bb.x);
                ffma2(a01, pl, bb.y);
                ffma2(a10, ph, bb.x);
                ffma2(a11, ph, bb.y);
            }
        }
        __syncthreads();
        issue(c + 2);
    }

    // Stage z: sZ[row][tc]
    {
        float2 u;
        u = unp2(a00);
        sZ[r2 * 17 + 4 * cgrp + 0] = u.x;
        sZ[r2 * 17 + 4 * cgrp + 1] = u.y;
        u = unp2(a01);
        sZ[r2 * 17 + 4 * cgrp + 2] = u.x;
        sZ[r2 * 17 + 4 * cgrp + 3] = u.y;
        u = unp2(a10);
        sZ[(r2 + 32) * 17 + 4 * cgrp + 0] = u.x;
        sZ[(r2 + 32) * 17 + 4 * cgrp + 1] = u.y;
        u = unp2(a11);
        sZ[(r2 + 32) * 17 + 4 * cgrp + 2] = u.x;
        sZ[(r2 + 32) * 17 + 4 * cgrp + 3] = u.y;
    }
    __syncthreads();

    // Gate phase: thread -> (row = tid>>1, two hc's).
    {
        const int row = tid >> 1;
        const int hcb = (tid & 1) * 2;
#pragma unroll
        for (int u = 0; u < 2; ++u) {
            const int hc = hcb + u;
            const int hcol = g * 4 + hc;
            float zi = sZ[row * 17 + hc] + bias[hcol];
            float zf = sZ[row * 17 + 4 + hc] + bias[H + hcol];
            float zg = sZ[row * 17 + 8 + hc] + bias[2 * H + hcol];
            float zo = sZ[row * 17 + 12 + hc] + bias[3 * H + hcol];
            float ig = 1.f / (1.f + expf(-zi));
            float fg = 1.f / (1.f + expf(-zf));
            float gg = TANH ? tanhf(zg) : fmaxf(zg, 0.f);
            float og = 1.f / (1.f + expf(-zo));
            float cp_ = (t == 0) ? 0.f : cbuf[row * H + hcol];
            float cn = fg * cp_ + ig * gg;
            cbuf[row * H + hcol] = cn;
            float hn = og * (TANH ? tanhf(cn) : fmaxf(cn, 0.f));
            hseq[((size_t)t * BATCH + row) * H + hcol] = hn;
            if (OUT && t == TSTEPS - 1) outp[row * H + hcol] = hn;
        }
    }
    __syncthreads();
}

// ---------------------------------------------------------------------------
// Fused persistent kernel, 424 CTAs:
// [0,128) L0 | [128,192) L1 | [192,320) L4 | [320,384) L5 |
// [384,416) L3 (2 tiles/CTA) | [416,424) L2 (2 tiles/CTA).
// ---------------------------------------------------------------------------
__global__ __launch_bounds__(128, 3) void fused_kernel(
    const float* __restrict__ x,
    const float* __restrict__ b0, const float* __restrict__ b1,
    const float* __restrict__ b2, const float* __restrict__ b3,
    const float* __restrict__ b4, const float* __restrict__ b5,
    float* __restrict__ outp) {
    __shared__ float4 sA[2 * 64 * 17];
    __shared__ float4 sB[2 * 256];
    __shared__ float sZ[64 * 17];

    const int bid = blockIdx.x;
    unsigned* cnt = &g_barrier[0];

    for (int s = 0; s < GSTEPS; ++s) {
        if (bid < 128) {
            int t = s;
            if ((unsigned)t < TSTEPS)
                layer_step<256, 512, false, true, false>(
                    bid, t, x, g_seq0, g_cell + 0 * BATCH * 512,
                    g_packed + OFF0, b0, nullptr, sA, sB, sZ);
        } else if (bid < 192) {
            int t = s - 1;
            if ((unsigned)t < TSTEPS)
                layer_step<512, 256, false, false, false>(
                    bid - 128, t, g_seq0, g_seq1, g_cell + 1 * BATCH * 512,
                    g_packed + OFF1, b1, nullptr, sA, sB, sZ);
        } else if (bid < 320) {
            int t = s - 4;
            if ((unsigned)t < TSTEPS)
                layer_step<256, 512, false, false, false>(
                    bid - 192, t, g_seq3, g_seq4, g_cell + 4 * BATCH * 512,
                    g_packed + OFF4, b4, nullptr, sA, sB, sZ);
        } else if (bid < 384) {
            int t = s - 5;
            if ((unsigned)t < TSTEPS)
                layer_step<512, 256, true, false, true>(
                    bid - 320, t, g_seq4, g_seq5, g_cell + 5 * BATCH * 512,
                    g_packed + OFF5, b5, outp, sA, sB, sZ);
        } else if (bid < 416) {
            int t = s - 3;
            if ((unsigned)t < TSTEPS) {
                int q = bid - 384;
                layer_step<64, 256, false, false, false>(
                    2 * q, t, g_seq2, g_seq3, g_cell + 3 * BATCH * 512,
                    g_packed + OFF3, b3, nullptr, sA, sB, sZ);
                layer_step<64, 256, false, false, false>(
                    2 * q + 1, t, g_seq2, g_seq3, g_cell + 3 * BATCH * 512,
                    g_packed + OFF3, b3, nullptr, sA, sB, sZ);
            }
        } else {
            int t = s - 2;
            if ((unsigned)t < TSTEPS) {
                int q = bid - 416;
                layer_step<256, 64, false, false, false>(
                    2 * q, t, g_seq1, g_seq2, g_cell + 2 * BATCH * 512,
                    g_packed + OFF2, b2, nullptr, sA, sB, sZ);
                layer_step<256, 64, false, false, false>(
                    2 * q + 1, t, g_seq1, g_seq2, g_cell + 2 * BATCH * 512,
                    g_packed + OFF2, b2, nullptr, sA, sB, sZ);
            }
        }
        grid_bar(cnt, (unsigned)(s + 1) * NCTA);
    }
}

// ---------------------------------------------------------------------------
extern "C" void kernel_launch(void* const* d_in, const int* in_sizes, int n_in,
                              void* d_out, int out_size) {
    (void)in_sizes; (void)n_in; (void)out_size;

    const float* x = (const float*)d_in[0];
    const float* W[6];
    const float* U[6];
    const float* b[6];
    for (int l = 0; l < 6; ++l) {
        W[l] = (const float*)d_in[1 + 3 * l];
        U[l] = (const float*)d_in[2 + 3 * l];
        b[l] = (const float*)d_in[3 + 3 * l];
    }

    float* pk;
    cudaGetSymbolAddress((void**)&pk, g_packed);

    init_counters<<<1, 32>>>();

    repack_kernel<256, 512><<<256, 256>>>(W[0], U[0], pk + OFF0);
    repack_kernel<512, 256><<<256, 256>>>(W[1], U[1], pk + OFF1);
    repack_kernel<256, 64><<<64, 256>>>(W[2], U[2], pk + OFF2);
    repack_kernel<64, 256><<<128, 256>>>(W[3], U[3], pk + OFF3);
    repack_kernel<256, 512><<<256, 256>>>(W[4], U[4], pk + OFF4);
    repack_kernel<512, 256><<<256, 256>>>(W[5], U[5], pk + OFF5);

    fused_kernel<<<NCTA, 128>>>(x, b[0], b[1], b[2], b[3], b[4], b[5],
                                (float*)d_out);
}

// round 13
// speedup vs baseline: 7.2767x; 1.9870x over previous
#include <cuda_runtime.h>
#include <cuda_bf16.h>
#include <math.h>
#include <stdint.h>
#include <string.h>

// ---------------------------------------------------------------------------
// LSTM autoencoder: fused persistent wavefront + bf16 split-precision tensor
// core GEMM (mma.sync.m16n8k16, fp32 accumulate, AhBh + AhBl + AlBh).
// Layers (I,H): L0(256,512) L1(512,256) L2(256,64) L3(64,256) L4(256,512)
//               L5(512,256).  B=64, T=256.
// Per tile: 64 batch rows x 16 z-cols (4 h-cols, all 4 gates). 424 CTAs.
// ---------------------------------------------------------------------------

#define BATCH 64
#define TSTEPS 256
#define NCTA 424
#define GSTEPS (TSTEPS + 5)

// Sequence buffers as bf16 hi/lo pairs, time-major [T][B][H]
__device__ __nv_bfloat16 g_s0h[TSTEPS * BATCH * 512], g_s0l[TSTEPS * BATCH * 512];
__device__ __nv_bfloat16 g_s1h[TSTEPS * BATCH * 256], g_s1l[TSTEPS * BATCH * 256];
__device__ __nv_bfloat16 g_s2h[TSTEPS * BATCH * 64],  g_s2l[TSTEPS * BATCH * 64];
__device__ __nv_bfloat16 g_s3h[TSTEPS * BATCH * 256], g_s3l[TSTEPS * BATCH * 256];
__device__ __nv_bfloat16 g_s4h[TSTEPS * BATCH * 512], g_s4l[TSTEPS * BATCH * 512];
__device__ __nv_bfloat16 g_s5h[TSTEPS * BATCH * 256], g_s5l[TSTEPS * BATCH * 256];
__device__ __nv_bfloat16 g_xh[TSTEPS * BATCH * 256],  g_xl[TSTEPS * BATCH * 256];
__device__ float g_cell[6 * BATCH * 512];
// Packed weights: per layer, per tile g (4 h-cols = 16 z-cols), per k64 chunk:
// 1024 u32 words = [c4(4)][nt(2)][half(2)][lane(32)][j(2)], each word a bf16
// pair (k0, k0+1) exactly matching the mma.sync m16n8k16 B fragment.
__device__ __align__(256) unsigned g_packed[5128192];
__device__ unsigned g_barrier[4];

#define OFF0 0
#define OFF1 1572864
#define OFF2 2359296
#define OFF3 2441216
#define OFF4 2768896
#define OFF5 4341760

// ---------------------------------------------------------------------------
__global__ void init_counters() {
    if (threadIdx.x < 4) g_barrier[threadIdx.x] = 0;
}

__device__ __forceinline__ unsigned short bits_of(__nv_bfloat16 v) {
    unsigned short s;
    memcpy(&s, &v, 2);
    return s;
}

// Repack W [I,4H], U [H,4H] into bf16 hi/lo B-fragment layout.
template <int I, int H>
__global__ void repack_kernel(const float* __restrict__ W,
                              const float* __restrict__ U,
                              unsigned* __restrict__ out) {
    constexpr int K = I + H;
    constexpr int N4 = 4 * H;
    constexpr int GW = (K >> 6) << 10;  // words per tile
    const int total = (H / 4) * GW;
    for (int w = blockIdx.x * blockDim.x + threadIdx.x; w < total;
         w += gridDim.x * blockDim.x) {
        int g = w / GW;
        int rem = w % GW;
        int chunk = rem >> 10;
        int r2 = rem & 1023;
        int c4 = r2 >> 8;
        int nt = (r2 >> 7) & 1;
        int half = (r2 >> 6) & 1;
        int lane = (r2 >> 1) & 31;
        int j = r2 & 1;
        int k0 = (chunk * 4 + c4) * 16 + (lane & 3) * 2 + j * 8;
        int n = nt * 8 + (lane >> 2);              // z-col = gate*4 + hc
        int col = (n >> 2) * H + g * 4 + (n & 3);  // original weight column
        float v0 = (k0 < I) ? W[k0 * N4 + col] : U[(k0 - I) * N4 + col];
        float v1 = (k0 + 1 < I) ? W[(k0 + 1) * N4 + col]
                                : U[(k0 + 1 - I) * N4 + col];
        __nv_bfloat16 h0 = __float2bfloat16(v0);
        __nv_bfloat16 h1 = __float2bfloat16(v1);
        unsigned short u0, u1;
        if (half == 0) {
            u0 = bits_of(h0);
            u1 = bits_of(h1);
        } else {
            u0 = bits_of(__float2bfloat16(v0 - __bfloat162float(h0)));
            u1 = bits_of(__float2bfloat16(v1 - __bfloat162float(h1)));
        }
        out[w] = (unsigned)u0 | ((unsigned)u1 << 16);
    }
}

// Split x [B][T][256] into time-major bf16 hi/lo [T][B][256].
__global__ void split_x(const float* __restrict__ x) {
    const int total = TSTEPS * BATCH * 256;
    for (int i = blockIdx.x * blockDim.x + threadIdx.x; i < total;
         i += gridDim.x * blockDim.x) {
        int t = i >> 14;
        int rem = i & 16383;
        int row = rem >> 8;
        int k = rem & 255;
        float v = x[row * 65536 + t * 256 + k];
        __nv_bfloat16 h = __float2bfloat16(v);
        g_xh[i] = h;
        g_xl[i] = __float2bfloat16(v - __bfloat162float(h));
    }
}

// ---------------------------------------------------------------------------
__device__ __forceinline__ void cp16(uint32_t saddr, const void* gaddr) {
    asm volatile("cp.async.cg.shared.global [%0], [%1], 16;"
                 :: "r"(saddr), "l"(gaddr) : "memory");
}
__device__ __forceinline__ void cp_commit() {
    asm volatile("cp.async.commit_group;" ::: "memory");
}
__device__ __forceinline__ void cp_wait1() {
    asm volatile("cp.async.wait_group 1;" ::: "memory");
}
__device__ __forceinline__ void ldsm4(uint32_t& r0, uint32_t& r1, uint32_t& r2,
                                      uint32_t& r3, uint32_t addr) {
    asm volatile("ldmatrix.sync.aligned.m8n8.x4.shared.b16 {%0,%1,%2,%3}, [%4];"
                 : "=r"(r0), "=r"(r1), "=r"(r2), "=r"(r3) : "r"(addr));
}
__device__ __forceinline__ void lds2(uint32_t& r0, uint32_t& r1, uint32_t addr) {
    asm volatile("ld.shared.v2.b32 {%0,%1}, [%2];"
                 : "=r"(r0), "=r"(r1) : "r"(addr));
}
__device__ __forceinline__ void hmma(float* d, uint32_t a0, uint32_t a1,
                                     uint32_t a2, uint32_t a3, uint32_t b0,
                                     uint32_t b1) {
    asm volatile(
        "mma.sync.aligned.m16n8k16.row.col.f32.bf16.bf16.f32 "
        "{%0,%1,%2,%3}, {%4,%5,%6,%7}, {%8,%9}, {%0,%1,%2,%3};"
        : "+f"(d[0]), "+f"(d[1]), "+f"(d[2]), "+f"(d[3])
        : "r"(a0), "r"(a1), "r"(a2), "r"(a3), "r"(b0), "r"(b1));
}
__device__ __forceinline__ void grid_bar(unsigned* cnt, unsigned target) {
    __syncthreads();
    if (threadIdx.x == 0) {
        asm volatile("red.release.gpu.global.add.u32 [%0], 1;"
                     :: "l"(cnt) : "memory");
        unsigned v;
        do {
            asm volatile("ld.acquire.gpu.global.u32 %0, [%1];"
                         : "=r"(v) : "l"(cnt) : "memory");
        } while (v < target);
    }
    __syncthreads();
}

// ---------------------------------------------------------------------------
// Shared arena layout (49152 B total):
//   A tiles: stage(2) x half(2) x [64 rows x 144 B] = 36864
//   B tiles: stage(2) x 4096                        =  8192  (off 36864)
//   Z:       64 x 16 fp32                           =  4096  (off 45056)
// ---------------------------------------------------------------------------
template <int I, int H, bool TANH, bool OUT>
__device__ __forceinline__ void layer_step(
    int g, int t,
    const __nv_bfloat16* __restrict__ xinh,
    const __nv_bfloat16* __restrict__ xinl,
    __nv_bfloat16* __restrict__ hqh, __nv_bfloat16* __restrict__ hql,
    float* __restrict__ cbuf, const unsigned* __restrict__ Bp,
    const float* __restrict__ bias, float* __restrict__ outp,
    unsigned char* arena) {
    constexpr int K = I + H;
    static_assert((I & 63) == 0 && (K & 63) == 0, "chunking");
    const int tid = threadIdx.x, lane = tid & 31, warp = tid >> 5;
    const uint32_t sbase = (uint32_t)__cvta_generic_to_shared(arena);
    const int nch = ((t == 0) ? I : K) >> 6;
    const unsigned* BpG = Bp + (size_t)g * ((K >> 6) << 10);
    const __nv_bfloat16* hh = hqh + (size_t)(t - 1) * BATCH * H;
    const __nv_bfloat16* hl = hql + (size_t)(t - 1) * BATCH * H;
    const __nv_bfloat16* xh = xinh + (size_t)t * BATCH * I;
    const __nv_bfloat16* xl = xinl + (size_t)t * BATCH * I;

    auto issue = [&](int c) {
        if (c < nch) {
            const int kc = c << 6;
            const __nv_bfloat16 *sh, *sl;
            int dim, off;
            if (kc < I) { sh = xh; sl = xl; dim = I; off = kc; }
            else        { sh = hh; sl = hl; dim = H; off = kc - I; }
            uint32_t ab = sbase + (uint32_t)((c & 1) * 18432);
#pragma unroll
            for (int i = 0; i < 4; ++i) {
                int q = tid + i * 128;
                int row = q >> 3, unit = q & 7;
                cp16(ab + row * 144 + unit * 16,
                     sh + (size_t)row * dim + off + unit * 8);
            }
#pragma unroll
            for (int i = 0; i < 4; ++i) {
                int q = tid + i * 128;
                int row = q >> 3, unit = q & 7;
                cp16(ab + 9216 + row * 144 + unit * 16,
                     sl + (size_t)row * dim + off + unit * 8);
            }
            uint32_t bb = sbase + 36864u + (uint32_t)((c & 1) * 4096);
#pragma unroll
            for (int i = 0; i < 2; ++i) {
                int q = tid + i * 128;
                cp16(bb + q * 16, BpG + (size_t)c * 1024 + q * 4);
            }
        }
        cp_commit();
    };

    float d0[4] = {0.f, 0.f, 0.f, 0.f};
    float d1[4] = {0.f, 0.f, 0.f, 0.f};

    const int sel = lane >> 3, rowin = lane & 7;
    const uint32_t aRow =
        (uint32_t)((warp * 16 + (sel & 1) * 8 + rowin) * 144 + (sel >> 1) * 16);

    issue(0);
    issue(1);

    for (int c = 0; c < nch; ++c) {
        cp_wait1();
        __syncthreads();
        uint32_t aH = sbase + (uint32_t)((c & 1) * 18432) + aRow;
        uint32_t aL = aH + 9216;
        uint32_t bB = sbase + 36864u + (uint32_t)((c & 1) * 4096) + lane * 8;
#pragma unroll
        for (int c4 = 0; c4 < 4; ++c4) {
            uint32_t ah0, ah1, ah2, ah3, al0, al1, al2, al3;
            ldsm4(ah0, ah1, ah2, ah3, aH + c4 * 32);
            ldsm4(al0, al1, al2, al3, aL + c4 * 32);
            uint32_t bo = bB + (uint32_t)(c4 * 1024);
            uint32_t bh0, bh1, bl0, bl1;
            lds2(bh0, bh1, bo);
            lds2(bl0, bl1, bo + 256);
            hmma(d0, ah0, ah1, ah2, ah3, bh0, bh1);
            hmma(d0, ah0, ah1, ah2, ah3, bl0, bl1);
            hmma(d0, al0, al1, al2, al3, bh0, bh1);
            lds2(bh0, bh1, bo + 512);
            lds2(bl0, bl1, bo + 768);
            hmma(d1, ah0, ah1, ah2, ah3, bh0, bh1);
            hmma(d1, ah0, ah1, ah2, ah3, bl0, bl1);
            hmma(d1, al0, al1, al2, al3, bh0, bh1);
        }
        __syncthreads();
        issue(c + 2);
    }

    // Epilogue: stage z into sZ[row][zcol], zcol = gate*4 + hc.
    float* sZ = reinterpret_cast<float*>(arena + 45056);
    {
        int r0 = warp * 16 + (lane >> 2);
        int c0 = (lane & 3) * 2;
        *reinterpret_cast<float2*>(&sZ[r0 * 16 + c0]) =
            make_float2(d0[0], d0[1]);
        *reinterpret_cast<float2*>(&sZ[(r0 + 8) * 16 + c0]) =
            make_float2(d0[2], d0[3]);
        *reinterpret_cast<float2*>(&sZ[r0 * 16 + 8 + c0]) =
            make_float2(d1[0], d1[1]);
        *reinterpret_cast<float2*>(&sZ[(r0 + 8) * 16 + 8 + c0]) =
            make_float2(d1[2], d1[3]);
    }
    __syncthreads();

    // Gate phase: thread -> (row = tid>>1, two h-cols).
    {
        const int row = tid >> 1;
        const int hcb = (tid & 1) * 2;
#pragma unroll
        for (int u = 0; u < 2; ++u) {
            const int hc = hcb + u;
            const int hcol = g * 4 + hc;
            float zi = sZ[row * 16 + hc] + bias[hcol];
            float zf = sZ[row * 16 + 4 + hc] + bias[H + hcol];
            float zg = sZ[row * 16 + 8 + hc] + bias[2 * H + hcol];
            float zo = sZ[row * 16 + 12 + hc] + bias[3 * H + hcol];
            float ig = 1.f / (1.f + expf(-zi));
            float fg = 1.f / (1.f + expf(-zf));
            float gg = TANH ? tanhf(zg) : fmaxf(zg, 0.f);
            float og = 1.f / (1.f + expf(-zo));
            float cp_ = (t == 0) ? 0.f : cbuf[row * H + hcol];
            float cn = fg * cp_ + ig * gg;
            cbuf[row * H + hcol] = cn;
            float hn = og * (TANH ? tanhf(cn) : fmaxf(cn, 0.f));
            size_t hidx = ((size_t)t * BATCH + row) * H + hcol;
            __nv_bfloat16 hb = __float2bfloat16(hn);
            hqh[hidx] = hb;
            hql[hidx] = __float2bfloat16(hn - __bfloat162float(hb));
            if (OUT && t == TSTEPS - 1) outp[row * H + hcol] = hn;
        }
    }
    __syncthreads();
}

// ---------------------------------------------------------------------------
// Fused persistent kernel, 424 CTAs:
// [0,128) L0 | [128,192) L1 | [192,320) L4 | [320,384) L5 |
// [384,416) L3 (2 tiles/CTA) | [416,424) L2 (2 tiles/CTA).
// ---------------------------------------------------------------------------
__global__ __launch_bounds__(128, 3) void fused_kernel(
    const float* __restrict__ b0, const float* __restrict__ b1,
    const float* __restrict__ b2, const float* __restrict__ b3,
    const float* __restrict__ b4, const float* __restrict__ b5,
    float* __restrict__ outp) {
    __shared__ __align__(16) unsigned char sArena[49152];

    const int bid = blockIdx.x;
    unsigned* cnt = &g_barrier[0];

    for (int s = 0; s < GSTEPS; ++s) {
        if (bid < 128) {
            int t = s;
            if ((unsigned)t < TSTEPS)
                layer_step<256, 512, false, false>(
                    bid, t, g_xh, g_xl, g_s0h, g_s0l,
                    g_cell + 0 * BATCH * 512, g_packed + OFF0, b0, nullptr,
                    sArena);
        } else if (bid < 192) {
            int t = s - 1;
            if ((unsigned)t < TSTEPS)
                layer_step<512, 256, false, false>(
                    bid - 128, t, g_s0h, g_s0l, g_s1h, g_s1l,
                    g_cell + 1 * BATCH * 512, g_packed + OFF1, b1, nullptr,
                    sArena);
        } else if (bid < 320) {
            int t = s - 4;
            if ((unsigned)t < TSTEPS)
                layer_step<256, 512, false, false>(
                    bid - 192, t, g_s3h, g_s3l, g_s4h, g_s4l,
                    g_cell + 4 * BATCH * 512, g_packed + OFF4, b4, nullptr,
                    sArena);
        } else if (bid < 384) {
            int t = s - 5;
            if ((unsigned)t < TSTEPS)
                layer_step<512, 256, true, true>(
                    bid - 320, t, g_s4h, g_s4l, g_s5h, g_s5l,
                    g_cell + 5 * BATCH * 512, g_packed + OFF5, b5, outp,
                    sArena);
        } else if (bid < 416) {
            int t = s - 3;
            if ((unsigned)t < TSTEPS) {
                int q = bid - 384;
                layer_step<64, 256, false, false>(
                    2 * q, t, g_s2h, g_s2l, g_s3h, g_s3l,
                    g_cell + 3 * BATCH * 512, g_packed + OFF3, b3, nullptr,
                    sArena);
                layer_step<64, 256, false, false>(
                    2 * q + 1, t, g_s2h, g_s2l, g_s3h, g_s3l,
                    g_cell + 3 * BATCH * 512, g_packed + OFF3, b3, nullptr,
                    sArena);
            }
        } else {
            int t = s - 2;
            if ((unsigned)t < TSTEPS) {
                int q = bid - 416;
                layer_step<256, 64, false, false>(
                    2 * q, t, g_s1h, g_s1l, g_s2h, g_s2l,
                    g_cell + 2 * BATCH * 512, g_packed + OFF2, b2, nullptr,
                    sArena);
                layer_step<256, 64, false, false>(
                    2 * q + 1, t, g_s1h, g_s1l, g_s2h, g_s2l,
                    g_cell + 2 * BATCH * 512, g_packed + OFF2, b2, nullptr,
                    sArena);
            }
        }
        grid_bar(cnt, (unsigned)(s + 1) * NCTA);
    }
}

// ---------------------------------------------------------------------------
extern "C" void kernel_launch(void* const* d_in, const int* in_sizes, int n_in,
                              void* d_out, int out_size) {
    (void)in_sizes; (void)n_in; (void)out_size;

    const float* x = (const float*)d_in[0];
    const float* W[6];
    const float* U[6];
    const float* b[6];
    for (int l = 0; l < 6; ++l) {
        W[l] = (const float*)d_in[1 + 3 * l];
        U[l] = (const float*)d_in[2 + 3 * l];
        b[l] = (const float*)d_in[3 + 3 * l];
    }

    unsigned* pk;
    cudaGetSymbolAddress((void**)&pk, g_packed);

    init_counters<<<1, 32>>>();
    split_x<<<512, 256>>>(x);

    repack_kernel<256, 512><<<512, 256>>>(W[0], U[0], pk + OFF0);
    repack_kernel<512, 256><<<512, 256>>>(W[1], U[1], pk + OFF1);
    repack_kernel<256, 64><<<128, 256>>>(W[2], U[2], pk + OFF2);
    repack_kernel<64, 256><<<128, 256>>>(W[3], U[3], pk + OFF3);
    repack_kernel<256, 512><<<512, 256>>>(W[4], U[4], pk + OFF4);
    repack_kernel<512, 256><<<512, 256>>>(W[5], U[5], pk + OFF5);

    fused_kernel<<<NCTA, 128>>>(b[0], b[1], b[2], b[3], b[4], b[5],
                                (float*)d_out);
}

// round 14
// speedup vs baseline: 7.9515x; 1.0927x over previous
#include <cuda_runtime.h>
#include <cuda_bf16.h>
#include <math.h>
#include <stdint.h>
#include <string.h>

// ---------------------------------------------------------------------------
// LSTM autoencoder: fused persistent wavefront + bf16 split-precision tensor
// core GEMM (mma.sync.m16n8k16 fp32-accum, AhBh + AhBl + AlBh).
// Tile per CTA: 64 batch rows x 32 z-cols (8 h-cols, all 4 gates). 232 CTAs.
// Layers (I,H): L0(256,512) L1(512,256) L2(256,64) L3(64,256) L4(256,512)
//               L5(512,256).  B=64, T=256. One grid barrier per global step.
// ---------------------------------------------------------------------------

#define BATCH 64
#define TSTEPS 256
#define NCTA 232
#define GSTEPS (TSTEPS + 5)
#define SMEM_BYTES 61952

// Sequence buffers as bf16 hi/lo pairs, time-major [T][B][H]
__device__ __nv_bfloat16 g_s0h[TSTEPS * BATCH * 512], g_s0l[TSTEPS * BATCH * 512];
__device__ __nv_bfloat16 g_s1h[TSTEPS * BATCH * 256], g_s1l[TSTEPS * BATCH * 256];
__device__ __nv_bfloat16 g_s2h[TSTEPS * BATCH * 64],  g_s2l[TSTEPS * BATCH * 64];
__device__ __nv_bfloat16 g_s3h[TSTEPS * BATCH * 256], g_s3l[TSTEPS * BATCH * 256];
__device__ __nv_bfloat16 g_s4h[TSTEPS * BATCH * 512], g_s4l[TSTEPS * BATCH * 512];
__device__ __nv_bfloat16 g_s5h[TSTEPS * BATCH * 256], g_s5l[TSTEPS * BATCH * 256];
__device__ __nv_bfloat16 g_xh[TSTEPS * BATCH * 256],  g_xl[TSTEPS * BATCH * 256];
__device__ float g_cell[6 * BATCH * 512];
// Packed weights: per layer, per tile g (8 h-cols = 32 z-cols), per k64 chunk:
// 2048 u32 words = [c4(4)][nt(4)][half(2)][lane(32)][j(2)]; each word a bf16
// pair (k0, k0+1) matching the m16n8k16 B fragment. nt == gate.
__device__ __align__(256) unsigned g_packed[5128192];
__device__ unsigned g_barrier[4];

#define OFF0 0
#define OFF1 1572864
#define OFF2 2359296
#define OFF3 2441216
#define OFF4 2768896
#define OFF5 4341760

// ---------------------------------------------------------------------------
__global__ void init_counters() {
    if (threadIdx.x < 4) g_barrier[threadIdx.x] = 0;
}

__device__ __forceinline__ unsigned short bits_of(__nv_bfloat16 v) {
    unsigned short s;
    memcpy(&s, &v, 2);
    return s;
}

// Repack W [I,4H], U [H,4H] into bf16 hi/lo B-fragment layout (32-col tiles).
template <int I, int H>
__global__ void repack_kernel(const float* __restrict__ W,
                              const float* __restrict__ U,
                              unsigned* __restrict__ out) {
    constexpr int K = I + H;
    constexpr int N4 = 4 * H;
    constexpr int GW = (K >> 6) << 11;  // words per tile
    const int total = (H / 8) * GW;
    for (int w = blockIdx.x * blockDim.x + threadIdx.x; w < total;
         w += gridDim.x * blockDim.x) {
        int g = w / GW;
        int rem = w % GW;
        int chunk = rem >> 11;
        int r2 = rem & 2047;
        int c4 = r2 >> 9;
        int nt = (r2 >> 7) & 3;          // = gate
        int half = (r2 >> 6) & 1;
        int lane = (r2 >> 1) & 31;
        int j = r2 & 1;
        int k0 = (chunk * 4 + c4) * 16 + (lane & 3) * 2 + j * 8;
        int hcol = g * 8 + (lane >> 2);
        int col = nt * H + hcol;
        float v0 = (k0 < I) ? W[k0 * N4 + col] : U[(k0 - I) * N4 + col];
        float v1 = (k0 + 1 < I) ? W[(k0 + 1) * N4 + col]
                                : U[(k0 + 1 - I) * N4 + col];
        __nv_bfloat16 h0 = __float2bfloat16(v0);
        __nv_bfloat16 h1 = __float2bfloat16(v1);
        unsigned short u0, u1;
        if (half == 0) {
            u0 = bits_of(h0);
            u1 = bits_of(h1);
        } else {
            u0 = bits_of(__float2bfloat16(v0 - __bfloat162float(h0)));
            u1 = bits_of(__float2bfloat16(v1 - __bfloat162float(h1)));
        }
        out[w] = (unsigned)u0 | ((unsigned)u1 << 16);
    }
}

// Split x [B][T][256] into time-major bf16 hi/lo [T][B][256].
__global__ void split_x(const float* __restrict__ x) {
    const int total = TSTEPS * BATCH * 256;
    for (int i = blockIdx.x * blockDim.x + threadIdx.x; i < total;
         i += gridDim.x * blockDim.x) {
        int t = i >> 14;
        int rem = i & 16383;
        int row = rem >> 8;
        int k = rem & 255;
        float v = x[row * 65536 + t * 256 + k];
        __nv_bfloat16 h = __float2bfloat16(v);
        g_xh[i] = h;
        g_xl[i] = __float2bfloat16(v - __bfloat162float(h));
    }
}

// ---------------------------------------------------------------------------
__device__ __forceinline__ void cp16(uint32_t saddr, const void* gaddr) {
    asm volatile("cp.async.cg.shared.global [%0], [%1], 16;"
                 :: "r"(saddr), "l"(gaddr) : "memory");
}
__device__ __forceinline__ void cp_commit() {
    asm volatile("cp.async.commit_group;" ::: "memory");
}
__device__ __forceinline__ void cp_wait1() {
    asm volatile("cp.async.wait_group 1;" ::: "memory");
}
__device__ __forceinline__ void ldsm4(uint32_t& r0, uint32_t& r1, uint32_t& r2,
                                      uint32_t& r3, uint32_t addr) {
    asm volatile("ldmatrix.sync.aligned.m8n8.x4.shared.b16 {%0,%1,%2,%3}, [%4];"
                 : "=r"(r0), "=r"(r1), "=r"(r2), "=r"(r3) : "r"(addr));
}
__device__ __forceinline__ void lds2(uint32_t& r0, uint32_t& r1, uint32_t addr) {
    asm volatile("ld.shared.v2.b32 {%0,%1}, [%2];"
                 : "=r"(r0), "=r"(r1) : "r"(addr));
}
__device__ __forceinline__ void hmma(float* d, uint32_t a0, uint32_t a1,
                                     uint32_t a2, uint32_t a3, uint32_t b0,
                                     uint32_t b1) {
    asm volatile(
        "mma.sync.aligned.m16n8k16.row.col.f32.bf16.bf16.f32 "
        "{%0,%1,%2,%3}, {%4,%5,%6,%7}, {%8,%9}, {%0,%1,%2,%3};"
        : "+f"(d[0]), "+f"(d[1]), "+f"(d[2]), "+f"(d[3])
        : "r"(a0), "r"(a1), "r"(a2), "r"(a3), "r"(b0), "r"(b1));
}
__device__ __forceinline__ void grid_bar(unsigned* cnt, unsigned target) {
    __syncthreads();
    if (threadIdx.x == 0) {
        asm volatile("red.release.gpu.global.add.u32 [%0], 1;"
                     :: "l"(cnt) : "memory");
        unsigned v;
        do {
            asm volatile("ld.acquire.gpu.global.u32 %0, [%1];"
                         : "=r"(v) : "l"(cnt) : "memory");
        } while (v < target);
    }
    __syncthreads();
}

// ---------------------------------------------------------------------------
// Shared arena layout (61952 B):
//   A: stage(2) x half(2) x [64 rows x 144 B] = 36864          (off 0)
//   B: stage(2) x 8192                        = 16384          (off 36864)
//   Z: 64 x 34 fp32                           =  8704          (off 53248)
// ---------------------------------------------------------------------------
template <int I, int H, bool TANH, bool OUT>
__device__ __forceinline__ void layer_step(
    int g, int t,
    const __nv_bfloat16* __restrict__ xinh,
    const __nv_bfloat16* __restrict__ xinl,
    __nv_bfloat16* __restrict__ hqh, __nv_bfloat16* __restrict__ hql,
    float* __restrict__ cbuf, const unsigned* __restrict__ Bp,
    const float* __restrict__ bias, float* __restrict__ outp,
    unsigned char* arena) {
    constexpr int K = I + H;
    static_assert((I & 63) == 0 && (K & 63) == 0, "chunking");
    const int tid = threadIdx.x, lane = tid & 31, warp = tid >> 5;
    const uint32_t sbase = (uint32_t)__cvta_generic_to_shared(arena);
    const int nch = ((t == 0) ? I : K) >> 6;
    const unsigned* BpG = Bp + (size_t)g * ((K >> 6) << 11);
    const __nv_bfloat16* hh = hqh + (size_t)(t - 1) * BATCH * H;
    const __nv_bfloat16* hl = hql + (size_t)(t - 1) * BATCH * H;
    const __nv_bfloat16* xh = xinh + (size_t)t * BATCH * I;
    const __nv_bfloat16* xl = xinl + (size_t)t * BATCH * I;

    auto issue = [&](int c) {
        if (c < nch) {
            const int kc = c << 6;
            const __nv_bfloat16 *sh, *sl;
            int dim, off;
            if (kc < I) { sh = xh; sl = xl; dim = I; off = kc; }
            else        { sh = hh; sl = hl; dim = H; off = kc - I; }
            uint32_t ab = sbase + (uint32_t)((c & 1) * 18432);
#pragma unroll
            for (int i = 0; i < 4; ++i) {
                int q = tid + i * 128;
                int row = q >> 3, unit = q & 7;
                cp16(ab + row * 144 + unit * 16,
                     sh + (size_t)row * dim + off + unit * 8);
            }
#pragma unroll
            for (int i = 0; i < 4; ++i) {
                int q = tid + i * 128;
                int row = q >> 3, unit = q & 7;
                cp16(ab + 9216 + row * 144 + unit * 16,
                     sl + (size_t)row * dim + off + unit * 8);
            }
            uint32_t bb = sbase + 36864u + (uint32_t)((c & 1) * 8192);
#pragma unroll
            for (int i = 0; i < 4; ++i) {
                int q = tid + i * 128;
                cp16(bb + q * 16, BpG + (size_t)c * 2048 + q * 4);
            }
        }
        cp_commit();
    };

    float d[4][4];
#pragma unroll
    for (int nt = 0; nt < 4; ++nt)
#pragma unroll
        for (int e = 0; e < 4; ++e) d[nt][e] = 0.f;

    const int sel = lane >> 3, rowin = lane & 7;
    const uint32_t aRow =
        (uint32_t)((warp * 16 + (sel & 1) * 8 + rowin) * 144 + (sel >> 1) * 16);

    issue(0);
    issue(1);

    for (int c = 0; c < nch; ++c) {
        cp_wait1();
        __syncthreads();
        uint32_t aH = sbase + (uint32_t)((c & 1) * 18432) + aRow;
        uint32_t aL = aH + 9216;
        uint32_t bB = sbase + 36864u + (uint32_t)((c & 1) * 8192) + lane * 8;
#pragma unroll
        for (int c4 = 0; c4 < 4; ++c4) {
            uint32_t ah0, ah1, ah2, ah3, al0, al1, al2, al3;
            ldsm4(ah0, ah1, ah2, ah3, aH + c4 * 32);
            ldsm4(al0, al1, al2, al3, aL + c4 * 32);
            uint32_t bo = bB + (uint32_t)(c4 * 8192 / 4);  // c4*2048 bytes
#pragma unroll
            for (int nt = 0; nt < 4; ++nt) {
                uint32_t bh0, bh1, bl0, bl1;
                lds2(bh0, bh1, bo + nt * 512);
                lds2(bl0, bl1, bo + nt * 512 + 256);
                hmma(d[nt], ah0, ah1, ah2, ah3, bh0, bh1);
                hmma(d[nt], ah0, ah1, ah2, ah3, bl0, bl1);
                hmma(d[nt], al0, al1, al2, al3, bh0, bh1);
            }
        }
        __syncthreads();
        issue(c + 2);
    }

    // Epilogue: stage z into sZ[row][zcol] (pitch 34), zcol = gate*8 + hc.
    float* sZ = reinterpret_cast<float*>(arena + 53248);
    {
        int r0 = warp * 16 + (lane >> 2);
        int c0 = (lane & 3) * 2;
#pragma unroll
        for (int nt = 0; nt < 4; ++nt) {
            *reinterpret_cast<float2*>(&sZ[r0 * 34 + nt * 8 + c0]) =
                make_float2(d[nt][0], d[nt][1]);
            *reinterpret_cast<float2*>(&sZ[(r0 + 8) * 34 + nt * 8 + c0]) =
                make_float2(d[nt][2], d[nt][3]);
        }
    }
    __syncthreads();

    // Gate phase: thread -> (row = tid>>1, four h-cols).
    {
        const int row = tid >> 1;
        const int hcb = (tid & 1) * 4;
#pragma unroll
        for (int u = 0; u < 4; ++u) {
            const int hc = hcb + u;
            const int hcol = g * 8 + hc;
            float zi = sZ[row * 34 + hc] + bias[hcol];
            float zf = sZ[row * 34 + 8 + hc] + bias[H + hcol];
            float zg = sZ[row * 34 + 16 + hc] + bias[2 * H + hcol];
            float zo = sZ[row * 34 + 24 + hc] + bias[3 * H + hcol];
            float ig = 1.f / (1.f + expf(-zi));
            float fg = 1.f / (1.f + expf(-zf));
            float gg = TANH ? tanhf(zg) : fmaxf(zg, 0.f);
            float og = 1.f / (1.f + expf(-zo));
            float cp_ = (t == 0) ? 0.f : cbuf[row * H + hcol];
            float cn = fg * cp_ + ig * gg;
            cbuf[row * H + hcol] = cn;
            float hn = og * (TANH ? tanhf(cn) : fmaxf(cn, 0.f));
            size_t hidx = ((size_t)t * BATCH + row) * H + hcol;
            __nv_bfloat16 hb = __float2bfloat16(hn);
            hqh[hidx] = hb;
            hql[hidx] = __float2bfloat16(hn - __bfloat162float(hb));
            if (OUT && t == TSTEPS - 1) outp[row * H + hcol] = hn;
        }
    }
    __syncthreads();
}

// ---------------------------------------------------------------------------
// Fused persistent kernel, 232 CTAs:
// [0,64) L0 | [64,96) L1 | [96,160) L4 | [160,192) L5 | [192,224) L3 |
// [224,232) L2.
// ---------------------------------------------------------------------------
__global__ __launch_bounds__(128, 2) void fused_kernel(
    const float* __restrict__ b0, const float* __restrict__ b1,
    const float* __restrict__ b2, const float* __restrict__ b3,
    const float* __restrict__ b4, const float* __restrict__ b5,
    float* __restrict__ outp) {
    extern __shared__ __align__(16) unsigned char sArena[];

    const int bid = blockIdx.x;
    unsigned* cnt = &g_barrier[0];

    for (int s = 0; s < GSTEPS; ++s) {
        if (bid < 64) {
            int t = s;
            if ((unsigned)t < TSTEPS)
                layer_step<256, 512, false, false>(
                    bid, t, g_xh, g_xl, g_s0h, g_s0l,
                    g_cell + 0 * BATCH * 512, g_packed + OFF0, b0, nullptr,
                    sArena);
        } else if (bid < 96) {
            int t = s - 1;
            if ((unsigned)t < TSTEPS)
                layer_step<512, 256, false, false>(
                    bid - 64, t, g_s0h, g_s0l, g_s1h, g_s1l,
                    g_cell + 1 * BATCH * 512, g_packed + OFF1, b1, nullptr,
                    sArena);
        } else if (bid < 160) {
            int t = s - 4;
            if ((unsigned)t < TSTEPS)
                layer_step<256, 512, false, false>(
                    bid - 96, t, g_s3h, g_s3l, g_s4h, g_s4l,
                    g_cell + 4 * BATCH * 512, g_packed + OFF4, b4, nullptr,
                    sArena);
        } else if (bid < 192) {
            int t = s - 5;
            if ((unsigned)t < TSTEPS)
                layer_step<512, 256, true, true>(
                    bid - 160, t, g_s4h, g_s4l, g_s5h, g_s5l,
                    g_cell + 5 * BATCH * 512, g_packed + OFF5, b5, outp,
                    sArena);
        } else if (bid < 224) {
            int t = s - 3;
            if ((unsigned)t < TSTEPS)
                layer_step<64, 256, false, false>(
                    bid - 192, t, g_s2h, g_s2l, g_s3h, g_s3l,
                    g_cell + 3 * BATCH * 512, g_packed + OFF3, b3, nullptr,
                    sArena);
        } else {
            int t = s - 2;
            if ((unsigned)t < TSTEPS)
                layer_step<256, 64, false, false>(
                    bid - 224, t, g_s1h, g_s1l, g_s2h, g_s2l,
                    g_cell + 2 * BATCH * 512, g_packed + OFF2, b2, nullptr,
                    sArena);
        }
        grid_bar(cnt, (unsigned)(s + 1) * NCTA);
    }
}

// ---------------------------------------------------------------------------
extern "C" void kernel_launch(void* const* d_in, const int* in_sizes, int n_in,
                              void* d_out, int out_size) {
    (void)in_sizes; (void)n_in; (void)out_size;

    const float* x = (const float*)d_in[0];
    const float* W[6];
    const float* U[6];
    const float* b[6];
    for (int l = 0; l < 6; ++l) {
        W[l] = (const float*)d_in[1 + 3 * l];
        U[l] = (const float*)d_in[2 + 3 * l];
        b[l] = (const float*)d_in[3 + 3 * l];
    }

    unsigned* pk;
    cudaGetSymbolAddress((void**)&pk, g_packed);

    cudaFuncSetAttribute(fused_kernel,
                         cudaFuncAttributeMaxDynamicSharedMemorySize,
                         SMEM_BYTES);

    init_counters<<<1, 32>>>();
    split_x<<<512, 256>>>(x);

    repack_kernel<256, 512><<<512, 256>>>(W[0], U[0], pk + OFF0);
    repack_kernel<512, 256><<<512, 256>>>(W[1], U[1], pk + OFF1);
    repack_kernel<256, 64><<<128, 256>>>(W[2], U[2], pk + OFF2);
    repack_kernel<64, 256><<<128, 256>>>(W[3], U[3], pk + OFF3);
    repack_kernel<256, 512><<<512, 256>>>(W[4], U[4], pk + OFF4);
    repack_kernel<512, 256><<<512, 256>>>(W[5], U[5], pk + OFF5);

    fused_kernel<<<NCTA, 128, SMEM_BYTES>>>(b[0], b[1], b[2], b[3], b[4], b[5],
                                            (float*)d_out);
}

// round 15
// speedup vs baseline: 8.6437x; 1.0871x over previous
#include <cuda_runtime.h>
#include <cuda_bf16.h>
#include <math.h>
#include <stdint.h>
#include <string.h>

// ---------------------------------------------------------------------------
// LSTM autoencoder: persistent kernel, bf16 split-precision tensor-core GEMM
// (mma.sync.m16n8k16 fp32-accum, AhBh + AhBl + AlBh), DECOUPLED layer sync.
// Each layer has its own completion counter; a CTA waits only on (a) its
// producer layer's counter for input_t, (b) its own layer's counter for
// h_{t-1}. x-chunks are loaded/computed before the own-layer wait.
// Tile per CTA: 64 batch rows x 32 z-cols. 232 CTAs.
// ---------------------------------------------------------------------------

#define BATCH 64
#define TSTEPS 256
#define NCTA 232
#define SMEM_BYTES 61952

// Sequence buffers as bf16 hi/lo pairs, time-major [T][B][H]
__device__ __nv_bfloat16 g_s0h[TSTEPS * BATCH * 512], g_s0l[TSTEPS * BATCH * 512];
__device__ __nv_bfloat16 g_s1h[TSTEPS * BATCH * 256], g_s1l[TSTEPS * BATCH * 256];
__device__ __nv_bfloat16 g_s2h[TSTEPS * BATCH * 64],  g_s2l[TSTEPS * BATCH * 64];
__device__ __nv_bfloat16 g_s3h[TSTEPS * BATCH * 256], g_s3l[TSTEPS * BATCH * 256];
__device__ __nv_bfloat16 g_s4h[TSTEPS * BATCH * 512], g_s4l[TSTEPS * BATCH * 512];
__device__ __nv_bfloat16 g_s5h[TSTEPS * BATCH * 256], g_s5l[TSTEPS * BATCH * 256];
__device__ __nv_bfloat16 g_xh[TSTEPS * BATCH * 256],  g_xl[TSTEPS * BATCH * 256];
__device__ float g_cell[6 * BATCH * 512];
// Packed weights: per layer, per tile g (8 h-cols = 32 z-cols), per k64 chunk:
// 2048 u32 words = [c4(4)][nt(4)][half(2)][lane(32)][j(2)]; each word a bf16
// pair (k0, k0+1) matching the m16n8k16 B fragment. nt == gate.
__device__ __align__(256) unsigned g_packed[5128192];
// Per-layer completion counters (monotonic within a replay).
__device__ unsigned g_done[8];

#define OFF0 0
#define OFF1 1572864
#define OFF2 2359296
#define OFF3 2441216
#define OFF4 2768896
#define OFF5 4341760

// ---------------------------------------------------------------------------
__global__ void init_counters() {
    if (threadIdx.x < 8) g_done[threadIdx.x] = 0;
}

__device__ __forceinline__ unsigned short bits_of(__nv_bfloat16 v) {
    unsigned short s;
    memcpy(&s, &v, 2);
    return s;
}

// Repack W [I,4H], U [H,4H] into bf16 hi/lo B-fragment layout (32-col tiles).
template <int I, int H>
__global__ void repack_kernel(const float* __restrict__ W,
                              const float* __restrict__ U,
                              unsigned* __restrict__ out) {
    constexpr int K = I + H;
    constexpr int N4 = 4 * H;
    constexpr int GW = (K >> 6) << 11;  // words per tile
    const int total = (H / 8) * GW;
    for (int w = blockIdx.x * blockDim.x + threadIdx.x; w < total;
         w += gridDim.x * blockDim.x) {
        int g = w / GW;
        int rem = w % GW;
        int chunk = rem >> 11;
        int r2 = rem & 2047;
        int c4 = r2 >> 9;
        int nt = (r2 >> 7) & 3;          // = gate
        int half = (r2 >> 6) & 1;
        int lane = (r2 >> 1) & 31;
        int j = r2 & 1;
        int k0 = (chunk * 4 + c4) * 16 + (lane & 3) * 2 + j * 8;
        int hcol = g * 8 + (lane >> 2);
        int col = nt * H + hcol;
        float v0 = (k0 < I) ? W[k0 * N4 + col] : U[(k0 - I) * N4 + col];
        float v1 = (k0 + 1 < I) ? W[(k0 + 1) * N4 + col]
                                : U[(k0 + 1 - I) * N4 + col];
        __nv_bfloat16 h0 = __float2bfloat16(v0);
        __nv_bfloat16 h1 = __float2bfloat16(v1);
        unsigned short u0, u1;
        if (half == 0) {
            u0 = bits_of(h0);
            u1 = bits_of(h1);
        } else {
            u0 = bits_of(__float2bfloat16(v0 - __bfloat162float(h0)));
            u1 = bits_of(__float2bfloat16(v1 - __bfloat162float(h1)));
        }
        out[w] = (unsigned)u0 | ((unsigned)u1 << 16);
    }
}

// Split x [B][T][256] into time-major bf16 hi/lo [T][B][256].
__global__ void split_x(const float* __restrict__ x) {
    const int total = TSTEPS * BATCH * 256;
    for (int i = blockIdx.x * blockDim.x + threadIdx.x; i < total;
         i += gridDim.x * blockDim.x) {
        int t = i >> 14;
        int rem = i & 16383;
        int row = rem >> 8;
        int k = rem & 255;
        float v = x[row * 65536 + t * 256 + k];
        __nv_bfloat16 h = __float2bfloat16(v);
        g_xh[i] = h;
        g_xl[i] = __float2bfloat16(v - __bfloat162float(h));
    }
}

// ---------------------------------------------------------------------------
__device__ __forceinline__ void cp16(uint32_t saddr, const void* gaddr) {
    asm volatile("cp.async.cg.shared.global [%0], [%1], 16;"
                 :: "r"(saddr), "l"(gaddr) : "memory");
}
__device__ __forceinline__ void cp_commit() {
    asm volatile("cp.async.commit_group;" ::: "memory");
}
__device__ __forceinline__ void cp_wait1() {
    asm volatile("cp.async.wait_group 1;" ::: "memory");
}
__device__ __forceinline__ void ldsm4(uint32_t& r0, uint32_t& r1, uint32_t& r2,
                                      uint32_t& r3, uint32_t addr) {
    asm volatile("ldmatrix.sync.aligned.m8n8.x4.shared.b16 {%0,%1,%2,%3}, [%4];"
                 : "=r"(r0), "=r"(r1), "=r"(r2), "=r"(r3) : "r"(addr));
}
__device__ __forceinline__ void lds2(uint32_t& r0, uint32_t& r1, uint32_t addr) {
    asm volatile("ld.shared.v2.b32 {%0,%1}, [%2];"
                 : "=r"(r0), "=r"(r1) : "r"(addr));
}
__device__ __forceinline__ void hmma(float* d, uint32_t a0, uint32_t a1,
                                     uint32_t a2, uint32_t a3, uint32_t b0,
                                     uint32_t b1) {
    asm volatile(
        "mma.sync.aligned.m16n8k16.row.col.f32.bf16.bf16.f32 "
        "{%0,%1,%2,%3}, {%4,%5,%6,%7}, {%8,%9}, {%0,%1,%2,%3};"
        : "+f"(d[0]), "+f"(d[1]), "+f"(d[2]), "+f"(d[3])
        : "r"(a0), "r"(a1), "r"(a2), "r"(a3), "r"(b0), "r"(b1));
}
__device__ __forceinline__ void spin_until(unsigned* cnt, unsigned target) {
    unsigned v;
    do {
        asm volatile("ld.acquire.gpu.global.u32 %0, [%1];"
                     : "=r"(v) : "l"(cnt) : "memory");
    } while (v < target);
}
__device__ __forceinline__ void arrive(unsigned* cnt) {
    asm volatile("red.release.gpu.global.add.u32 [%0], 1;"
                 :: "l"(cnt) : "memory");
}

// ---------------------------------------------------------------------------
// Shared arena layout (61952 B):
//   A: stage(2) x half(2) x [64 rows x 144 B] = 36864          (off 0)
//   B: stage(2) x 8192                        = 16384          (off 36864)
//   Z: 64 x 34 fp32                           =  8704          (off 53248)
// ---------------------------------------------------------------------------
template <int I, int H, bool TANH, bool OUT>
__device__ __forceinline__ void layer_step(
    int g, int t,
    const __nv_bfloat16* __restrict__ xinh,
    const __nv_bfloat16* __restrict__ xinl,
    __nv_bfloat16* __restrict__ hqh, __nv_bfloat16* __restrict__ hql,
    float* __restrict__ cbuf, const unsigned* __restrict__ Bp,
    const float* __restrict__ bias, float* __restrict__ outp,
    unsigned char* arena,
    unsigned* ownCnt, unsigned ownN, unsigned* prodCnt, unsigned prodN) {
    constexpr int K = I + H;
    constexpr int HCHUNK = I >> 6;  // first h chunk index
    static_assert((I & 63) == 0 && (K & 63) == 0, "chunking");
    const int tid = threadIdx.x, lane = tid & 31, warp = tid >> 5;
    const uint32_t sbase = (uint32_t)__cvta_generic_to_shared(arena);
    const int nch = ((t == 0) ? I : K) >> 6;
    const unsigned* BpG = Bp + (size_t)g * ((K >> 6) << 11);
    const __nv_bfloat16* hh = hqh + (size_t)(t - 1) * BATCH * H;
    const __nv_bfloat16* hl = hql + (size_t)(t - 1) * BATCH * H;
    const __nv_bfloat16* xh = xinh + (size_t)t * BATCH * I;
    const __nv_bfloat16* xl = xinl + (size_t)t * BATCH * I;

    // Wait for this timestep's input from the producer layer.
    if (prodCnt) {
        if (tid == 0) spin_until(prodCnt, (unsigned)(t + 1) * prodN);
        __syncthreads();
    }

    auto issue = [&](int c) {
        if (c < nch) {
            const int kc = c << 6;
            const __nv_bfloat16 *sh, *sl;
            int dim, off;
            if (kc < I) { sh = xh; sl = xl; dim = I; off = kc; }
            else        { sh = hh; sl = hl; dim = H; off = kc - I; }
            uint32_t ab = sbase + (uint32_t)((c & 1) * 18432);
#pragma unroll
            for (int i = 0; i < 4; ++i) {
                int q = tid + i * 128;
                int row = q >> 3, unit = q & 7;
                cp16(ab + row * 144 + unit * 16,
                     sh + (size_t)row * dim + off + unit * 8);
            }
#pragma unroll
            for (int i = 0; i < 4; ++i) {
                int q = tid + i * 128;
                int row = q >> 3, unit = q & 7;
                cp16(ab + 9216 + row * 144 + unit * 16,
                     sl + (size_t)row * dim + off + unit * 8);
            }
            uint32_t bb = sbase + 36864u + (uint32_t)((c & 1) * 8192);
#pragma unroll
            for (int i = 0; i < 4; ++i) {
                int q = tid + i * 128;
                cp16(bb + q * 16, BpG + (size_t)c * 2048 + q * 4);
            }
        }
        cp_commit();
    };

    // Before issuing the first h-chunk, wait for own layer's step t-1.
    auto wait_h = [&](int j) {
        if (j == HCHUNK && t > 0) {
            if (tid == 0) spin_until(ownCnt, (unsigned)t * ownN);
            __syncthreads();
        }
    };

    float d[4][4];
#pragma unroll
    for (int nt = 0; nt < 4; ++nt)
#pragma unroll
        for (int e = 0; e < 4; ++e) d[nt][e] = 0.f;

    const int sel = lane >> 3, rowin = lane & 7;
    const uint32_t aRow =
        (uint32_t)((warp * 16 + (sel & 1) * 8 + rowin) * 144 + (sel >> 1) * 16);

    wait_h(0);
    issue(0);
    wait_h(1);
    issue(1);

    for (int c = 0; c < nch; ++c) {
        cp_wait1();
        __syncthreads();
        uint32_t aH = sbase + (uint32_t)((c & 1) * 18432) + aRow;
        uint32_t aL = aH + 9216;
        uint32_t bB = sbase + 36864u + (uint32_t)((c & 1) * 8192) + lane * 8;
#pragma unroll
        for (int c4 = 0; c4 < 4; ++c4) {
            uint32_t ah0, ah1, ah2, ah3, al0, al1, al2, al3;
            ldsm4(ah0, ah1, ah2, ah3, aH + c4 * 32);
            ldsm4(al0, al1, al2, al3, aL + c4 * 32);
            uint32_t bo = bB + (uint32_t)(c4 * 2048);
#pragma unroll
            for (int nt = 0; nt < 4; ++nt) {
                uint32_t bh0, bh1, bl0, bl1;
                lds2(bh0, bh1, bo + nt * 512);
                lds2(bl0, bl1, bo + nt * 512 + 256);
                hmma(d[nt], ah0, ah1, ah2, ah3, bh0, bh1);
                hmma(d[nt], ah0, ah1, ah2, ah3, bl0, bl1);
                hmma(d[nt], al0, al1, al2, al3, bh0, bh1);
            }
        }
        __syncthreads();
        wait_h(c + 2);
        issue(c + 2);
    }

    // Epilogue: stage z into sZ[row][zcol] (pitch 34), zcol = gate*8 + hc.
    float* sZ = reinterpret_cast<float*>(arena + 53248);
    {
        int r0 = warp * 16 + (lane >> 2);
        int c0 = (lane & 3) * 2;
#pragma unroll
        for (int nt = 0; nt < 4; ++nt) {
            *reinterpret_cast<float2*>(&sZ[r0 * 34 + nt * 8 + c0]) =
                make_float2(d[nt][0], d[nt][1]);
            *reinterpret_cast<float2*>(&sZ[(r0 + 8) * 34 + nt * 8 + c0]) =
                make_float2(d[nt][2], d[nt][3]);
        }
    }
    __syncthreads();

    // Gate phase: thread -> (row = tid>>1, four h-cols).
    {
        const int row = tid >> 1;
        const int hcb = (tid & 1) * 4;
#pragma unroll
        for (int u = 0; u < 4; ++u) {
            const int hc = hcb + u;
            const int hcol = g * 8 + hc;
            float zi = sZ[row * 34 + hc] + bias[hcol];
            float zf = sZ[row * 34 + 8 + hc] + bias[H + hcol];
            float zg = sZ[row * 34 + 16 + hc] + bias[2 * H + hcol];
            float zo = sZ[row * 34 + 24 + hc] + bias[3 * H + hcol];
            float ig = 1.f / (1.f + expf(-zi));
            float fg = 1.f / (1.f + expf(-zf));
            float gg = TANH ? tanhf(zg) : fmaxf(zg, 0.f);
            float og = 1.f / (1.f + expf(-zo));
            float cp_ = (t == 0) ? 0.f : cbuf[row * H + hcol];
            float cn = fg * cp_ + ig * gg;
            cbuf[row * H + hcol] = cn;
            float hn = og * (TANH ? tanhf(cn) : fmaxf(cn, 0.f));
            size_t hidx = ((size_t)t * BATCH + row) * H + hcol;
            __nv_bfloat16 hb = __float2bfloat16(hn);
            hqh[hidx] = hb;
            hql[hidx] = __float2bfloat16(hn - __bfloat162float(hb));
            if (OUT && t == TSTEPS - 1) outp[row * H + hcol] = hn;
        }
    }
    __syncthreads();          // all writes done block-wide
    if (tid == 0) arrive(ownCnt);  // publish step t completion
}

// ---------------------------------------------------------------------------
// Persistent kernel, 232 CTAs, each loops over its OWN t (no global step):
// [0,64) L0 | [64,96) L1 | [96,160) L4 | [160,192) L5 | [192,224) L3 |
// [224,232) L2.
// ---------------------------------------------------------------------------
__global__ __launch_bounds__(128, 2) void fused_kernel(
    const float* __restrict__ b0, const float* __restrict__ b1,
    const float* __restrict__ b2, const float* __restrict__ b3,
    const float* __restrict__ b4, const float* __restrict__ b5,
    float* __restrict__ outp) {
    extern __shared__ __align__(16) unsigned char sArena[];

    const int bid = blockIdx.x;

    if (bid < 64) {
        for (int t = 0; t < TSTEPS; ++t)
            layer_step<256, 512, false, false>(
                bid, t, g_xh, g_xl, g_s0h, g_s0l, g_cell + 0 * BATCH * 512,
                g_packed + OFF0, b0, nullptr, sArena, g_done + 0, 64, nullptr,
                0);
    } else if (bid < 96) {
        for (int t = 0; t < TSTEPS; ++t)
            layer_step<512, 256, false, false>(
                bid - 64, t, g_s0h, g_s0l, g_s1h, g_s1l,
                g_cell + 1 * BATCH * 512, g_packed + OFF1, b1, nullptr, sArena,
                g_done + 1, 32, g_done + 0, 64);
    } else if (bid < 160) {
        for (int t = 0; t < TSTEPS; ++t)
            layer_step<256, 512, false, false>(
                bid - 96, t, g_s3h, g_s3l, g_s4h, g_s4l,
                g_cell + 4 * BATCH * 512, g_packed + OFF4, b4, nullptr, sArena,
                g_done + 4, 64, g_done + 3, 32);
    } else if (bid < 192) {
        for (int t = 0; t < TSTEPS; ++t)
            layer_step<512, 256, true, true>(
                bid - 160, t, g_s4h, g_s4l, g_s5h, g_s5l,
                g_cell + 5 * BATCH * 512, g_packed + OFF5, b5, outp, sArena,
                g_done + 5, 32, g_done + 4, 64);
    } else if (bid < 224) {
        for (int t = 0; t < TSTEPS; ++t)
            layer_step<64, 256, false, false>(
                bid - 192, t, g_s2h, g_s2l, g_s3h, g_s3l,
                g_cell + 3 * BATCH * 512, g_packed + OFF3, b3, nullptr, sArena,
                g_done + 3, 32, g_done + 2, 8);
    } else {
        for (int t = 0; t < TSTEPS; ++t)
            layer_step<256, 64, false, false>(
                bid - 224, t, g_s1h, g_s1l, g_s2h, g_s2l,
                g_cell + 2 * BATCH * 512, g_packed + OFF2, b2, nullptr, sArena,
                g_done + 2, 8, g_done + 1, 32);
    }
}

// ---------------------------------------------------------------------------
extern "C" void kernel_launch(void* const* d_in, const int* in_sizes, int n_in,
                              void* d_out, int out_size) {
    (void)in_sizes; (void)n_in; (void)out_size;

    const float* x = (const float*)d_in[0];
    const float* W[6];
    const float* U[6];
    const float* b[6];
    for (int l = 0; l < 6; ++l) {
        W[l] = (const float*)d_in[1 + 3 * l];
        U[l] = (const float*)d_in[2 + 3 * l];
        b[l] = (const float*)d_in[3 + 3 * l];
    }

    unsigned* pk;
    cudaGetSymbolAddress((void**)&pk, g_packed);

    cudaFuncSetAttribute(fused_kernel,
                         cudaFuncAttributeMaxDynamicSharedMemorySize,
                         SMEM_BYTES);

    init_counters<<<1, 32>>>();
    split_x<<<512, 256>>>(x);

    repack_kernel<256, 512><<<512, 256>>>(W[0], U[0], pk + OFF0);
    repack_kernel<512, 256><<<512, 256>>>(W[1], U[1], pk + OFF1);
    repack_kernel<256, 64><<<128, 256>>>(W[2], U[2], pk + OFF2);
    repack_kernel<64, 256><<<128, 256>>>(W[3], U[3], pk + OFF3);
    repack_kernel<256, 512><<<512, 256>>>(W[4], U[4], pk + OFF4);
    repack_kernel<512, 256><<<512, 256>>>(W[5], U[5], pk + OFF5);

    fused_kernel<<<NCTA, 128, SMEM_BYTES>>>(b[0], b[1], b[2], b[3], b[4], b[5],
                                            (float*)d_out);
}